// round 16
// baseline (speedup 1.0000x reference)
#include <cuda_runtime.h>
#include <cuda_fp16.h>
#include <cstdint>
#include <cfloat>

// Fused conv2d 3x3 SAME -> min over C_out -> *2 via pipelined mma.sync FP16
// (m16n8k16, f32 accumulate). x:(32,64,128,128) f32, W:(128,64,3,3) f32.
//
// Round 16 = R14 with the A image re-grouped so each pixel's 4 fragment ics
// {i0,i0+1,i0+8,i0+9} are contiguous 8B -> (a0,a2)/(a1,a3) load as LDS.64:
//  - A LDS issues halved (16 -> 8 per warp-k-step), same bytes/wavefronts
//  - slot = 1056B (130 px x 8B + pad); t-stride == 8 words mod 32 and
//    half-warp addresses 8t+2q+{0,1} cover 32 banks -> conflict-free LDS.64
//  - boundary zeros baked into padded rows (words 0,129): no smem pre-zeroing
//  - W2h / B path / 4-chunk pipeline / epilogue identical to R14 (197us)

#define TPB 256

static constexpr int SLOT_B = 1056;                 // 130 px x 8B + 16 pad
static constexpr int A_BUF  = 12 * SLOT_B;          // 12672 (3 ky x 4 groups)
static constexpr int B_OFF  = 2 * A_BUF;            // 25344
static constexpr int B_SLAB = 9 * 4096;             // 36864
static constexpr int RED_OFF = B_OFF + 2 * B_SLAB;  // 99072
static constexpr int SMEM_TOTAL = RED_OFF + 2048;   // 101120 (2 CTA/SM)

static constexpr int QROW   = 520;                  // halves per padded row (1040B)
static constexpr int G_STRH = 128 * QROW;           // halves per (b,G) plane
static constexpr int CG_STRH = 4 * G_STRH;          // halves per ic-group (4 G)

__device__ __align__(16) __half x16q[34078720];     // 32 b x 16 G x 128 x 520
__device__ __half W2h[4 * 18432];

__device__ __forceinline__ uint32_t smem_u32(const void* p) {
    uint32_t a;
    asm("{ .reg .u64 t; cvta.to.shared.u64 t, %1; cvt.u32.u64 %0, t; }" : "=r"(a) : "l"(p));
    return a;
}
__device__ __forceinline__ void mma_f16(float& d0, float& d1, float& d2, float& d3,
                                        uint32_t a0, uint32_t a1, uint32_t a2, uint32_t a3,
                                        uint32_t b0, uint32_t b1) {
    asm volatile(
        "mma.sync.aligned.m16n8k16.row.col.f32.f16.f16.f32 "
        "{%0,%1,%2,%3}, {%4,%5,%6,%7}, {%8,%9}, {%0,%1,%2,%3};"
        : "+f"(d0), "+f"(d1), "+f"(d2), "+f"(d3)
        : "r"(a0), "r"(a1), "r"(a2), "r"(a3), "r"(b0), "r"(b1));
}

// ---- pre-kernel 1: x -> ic-quad-grouped padded fp16 image ----
// group G = cg*4 + qq holds ics {16cg+2qq, +1, +8, +9}; 8B per pixel.
// padded row: word w = pixel w-1 (word 0 and 129 are zeros).
__global__ void xq_kernel(const float* __restrict__ x) {
    int idx = blockIdx.x * TPB + threadIdx.x;       // one 16B chunk = 2 pixels
    int w16 = idx % 65;
    int rr  = idx / 65;
    int gy  = rr & 127;
    int rr2 = rr >> 7;
    int G   = rr2 & 15;
    int b   = rr2 >> 4;
    int cg = G >> 2, qq = G & 3;
    int i0 = cg * 16 + 2 * qq;
    const float* r0 = x + ((size_t)(b * 64 + i0) * 128 + gy) * 128;
    const float* r1 = r0 + 16384;
    const float* r2 = r0 + 8 * 16384;
    const float* r3 = r2 + 16384;
    uint32_t w[4];
#pragma unroll
    for (int e = 0; e < 2; ++e) {
        int px = 2 * w16 + e - 1;
        bool ok = (unsigned)px < 128u;
        float v0 = ok ? r0[px] : 0.f;
        float v1 = ok ? r1[px] : 0.f;
        float v2 = ok ? r2[px] : 0.f;
        float v3 = ok ? r3[px] : 0.f;
        __half2 lo = __floats2half2_rn(v0, v1);
        __half2 hi = __floats2half2_rn(v2, v3);
        w[2 * e]     = *reinterpret_cast<uint32_t*>(&lo);
        w[2 * e + 1] = *reinterpret_cast<uint32_t*>(&hi);
    }
    size_t off = ((size_t)(b * 16 + G) * 128 + gy) * QROW + (size_t)w16 * 8;
    *reinterpret_cast<uint4*>(x16q + off) = make_uint4(w[0], w[1], w[2], w[3]);
}

// ---- pre-kernel 2: W -> fragment-ordered fp16 W2h (identical to R14) ----
__global__ void wxform_kernel(const float* __restrict__ Wt) {
    int f = blockIdx.x * TPB + threadIdx.x;
    if (f >= 4 * 18432) return;
    int c = f / 18432;
    int r = f - c * 18432;
    int st = r >> 11;
    int u  = r & 2047;
    int ky = st / 3, kx = st - 3 * ky;
    int unit = u >> 3, h = u & 7;
    int lane = unit & 31, rest = unit >> 5;
    int wn = rest >> 1, j = rest & 1;
    int word = h >> 1, hw = h & 1;
    int nt = wn * 4 + j * 2 + (word >> 1);
    int breg = word & 1;
    int t = lane & 3, q = lane >> 2;
    int oc  = nt * 8 + q;
    int ipl = t + 4 * breg;
    int ic  = c * 16 + ipl * 2 + hw;
    W2h[f] = __float2half_rn(Wt[oc * 576 + ic * 9 + ky * 3 + kx]);
}

__global__ void __launch_bounds__(TPB, 2)
conv_min_mma13_kernel(float* __restrict__ out)
{
    extern __shared__ char smem[];
    const uint32_t sb = smem_u32(smem);
    const int tid    = threadIdx.x;
    const int lane   = tid & 31;
    const int wid    = tid >> 5;
    const int warp_m = wid >> 2;   // 0..1
    const int warp_n = wid & 3;    // 0..3
    const int q = lane >> 2;
    const int t = lane & 3;
    const int y = blockIdx.x;
    const int b = blockIdx.y;

    // per-lane A gather base: group slot t, pixel word (warp_m*64 + q)
    const uint32_t laneA = (uint32_t)(t * SLOT_B + (warp_m * 64 + q) * 8);

    // ---- per-thread A-fill descriptors: 780 16B-chunks per ic-group ----
    const __half* f_src[4];
    uint32_t f_dst[4];
    bool f_ok[4], f_val[4];
#pragma unroll
    for (int i = 0; i < 4; ++i) {
        int ch = tid + TPB * i;
        f_val[i] = (ch < 780);
        int chc  = f_val[i] ? ch : 0;
        int slot = chc / 65, w16 = chc - slot * 65;
        int kyr = slot >> 2, qq = slot & 3;
        int gy = y + kyr - 1;
        f_ok[i]  = f_val[i] && ((unsigned)gy < 128u);
        f_dst[i] = (uint32_t)(slot * SLOT_B + w16 * 16);
        f_src[i] = f_ok[i]
            ? x16q + (((size_t)(b * 16 + qq) * 128 + gy) * QROW + (size_t)w16 * 8)
            : x16q;
    }

    float acc[4][4][4];
#pragma unroll
    for (int mt = 0; mt < 4; ++mt)
#pragma unroll
        for (int nt = 0; nt < 4; ++nt)
#pragma unroll
            for (int r = 0; r < 4; ++r) acc[mt][nt][r] = 0.0f;

    // ---- prologue: group0 = A(0)+B(0); group1 = A(1)+B(1) ----
#pragma unroll
    for (int cc = 0; cc < 2; ++cc) {
        size_t adv = (size_t)cc * CG_STRH;
        uint32_t ab = sb + (uint32_t)(cc * A_BUF);
#pragma unroll
        for (int i = 0; i < 4; ++i) {
            if (f_val[i]) {
                const __half* sp = f_ok[i] ? (f_src[i] + adv) : x16q;
                uint32_t sz = f_ok[i] ? 16u : 0u;
                uint64_t g64 = __cvta_generic_to_global((const void*)sp);
                asm volatile("cp.async.cg.shared.global [%0], [%1], 16, %2;"
                             :: "r"(ab + f_dst[i]), "l"(g64), "r"(sz) : "memory");
            }
        }
        uint32_t bdst = sb + B_OFF + (uint32_t)(cc * B_SLAB);
        const __half* bsrc = W2h + cc * 18432;
#pragma unroll
        for (int i = 0; i < 9; ++i) {
            int j = tid + TPB * i;
            uint64_t g64 = __cvta_generic_to_global((const void*)(bsrc + j * 8));
            asm volatile("cp.async.cg.shared.global [%0], [%1], 16;"
                         :: "r"(bdst + (uint32_t)(j * 16)), "l"(g64) : "memory");
        }
        asm volatile("cp.async.commit_group;" ::: "memory");
    }

#pragma unroll 1
    for (int c = 0; c < 4; ++c) {
        asm volatile("cp.async.wait_group 1;" ::: "memory");
        __syncthreads();

        // ---- compute chunk c: 9 k16-steps (ky, kx) ----
        const uint32_t aC = sb + (uint32_t)((c & 1) * A_BUF) + laneA;
        const uint32_t bC = sb + B_OFF + (uint32_t)((c & 1) * B_SLAB) +
                            (uint32_t)(warp_n * 1024 + lane * 16);
#pragma unroll
        for (int ky = 0; ky < 3; ++ky) {
            const uint32_t aKy = aC + (uint32_t)(ky * (4 * SLOT_B));
#pragma unroll
            for (int kx = 0; kx < 3; ++kx) {
                const uint32_t aS = aKy + (uint32_t)(kx * 8);
                const uint32_t bS = bC + (uint32_t)((ky * 3 + kx) * 4096);
                uint32_t a0[4], a1[4], a2[4], a3[4];
#pragma unroll
                for (int mt = 0; mt < 4; ++mt) {
                    uint32_t base = aS + (uint32_t)(mt * 128);
                    asm volatile("ld.shared.v2.b32 {%0,%1}, [%2];"
                                 : "=r"(a0[mt]), "=r"(a2[mt]) : "r"(base));
                    asm volatile("ld.shared.v2.b32 {%0,%1}, [%2];"
                                 : "=r"(a1[mt]), "=r"(a3[mt]) : "r"(base + 64));
                }
                uint32_t b0[4], b1[4];
#pragma unroll
                for (int j = 0; j < 2; ++j) {
                    uint32_t addr = bS + (uint32_t)(j * 512);
                    asm volatile("ld.shared.v4.b32 {%0,%1,%2,%3}, [%4];"
                                 : "=r"(b0[2 * j]), "=r"(b1[2 * j]),
                                   "=r"(b0[2 * j + 1]), "=r"(b1[2 * j + 1])
                                 : "r"(addr));
                }
#pragma unroll
                for (int mt = 0; mt < 4; ++mt)
#pragma unroll
                    for (int nt = 0; nt < 4; ++nt)
                        mma_f16(acc[mt][nt][0], acc[mt][nt][1],
                                acc[mt][nt][2], acc[mt][nt][3],
                                a0[mt], a1[mt], a2[mt], a3[mt], b0[nt], b1[nt]);
            }
        }

        // all warps done reading parity-c buffers -> safe to refill
        __syncthreads();
        if (c + 2 < 4) {
            size_t adv = (size_t)(c + 2) * CG_STRH;
            uint32_t ab = sb + (uint32_t)((c & 1) * A_BUF);
#pragma unroll
            for (int i = 0; i < 4; ++i) {
                if (f_val[i]) {
                    const __half* sp = f_ok[i] ? (f_src[i] + adv) : x16q;
                    uint32_t sz = f_ok[i] ? 16u : 0u;
                    uint64_t g64 = __cvta_generic_to_global((const void*)sp);
                    asm volatile("cp.async.cg.shared.global [%0], [%1], 16, %2;"
                                 :: "r"(ab + f_dst[i]), "l"(g64), "r"(sz) : "memory");
                }
            }
            uint32_t bdst = sb + B_OFF + (uint32_t)((c & 1) * B_SLAB);
            const __half* bsrc = W2h + (c + 2) * 18432;
#pragma unroll
            for (int i = 0; i < 9; ++i) {
                int j = tid + TPB * i;
                uint64_t g64 = __cvta_generic_to_global((const void*)(bsrc + j * 8));
                asm volatile("cp.async.cg.shared.global [%0], [%1], 16;"
                             :: "r"(bdst + (uint32_t)(j * 16)), "l"(g64) : "memory");
            }
        }
        asm volatile("cp.async.commit_group;" ::: "memory");
    }

    // ---- epilogue: min over oc, *2, write ----
    float rmin[4][2];
#pragma unroll
    for (int mt = 0; mt < 4; ++mt) {
        float lo = fminf(acc[mt][0][0], acc[mt][0][1]);
        float hi = fminf(acc[mt][0][2], acc[mt][0][3]);
#pragma unroll
        for (int nt = 1; nt < 4; ++nt) {
            lo = fminf(lo, fminf(acc[mt][nt][0], acc[mt][nt][1]));
            hi = fminf(hi, fminf(acc[mt][nt][2], acc[mt][nt][3]));
        }
        rmin[mt][0] = lo;
        rmin[mt][1] = hi;
    }
#pragma unroll
    for (int d = 1; d <= 2; d <<= 1)
#pragma unroll
        for (int mt = 0; mt < 4; ++mt)
#pragma unroll
            for (int h = 0; h < 2; ++h)
                rmin[mt][h] = fminf(rmin[mt][h],
                                    __shfl_xor_sync(0xffffffffu, rmin[mt][h], d));

    float* red = reinterpret_cast<float*>(smem + RED_OFF);
    __syncthreads();
    if ((lane & 3) == 0) {
        int gq = lane >> 2;
#pragma unroll
        for (int mt = 0; mt < 4; ++mt)
#pragma unroll
            for (int h = 0; h < 2; ++h) {
                int row = (warp_m * 4 + mt) * 16 + h * 8 + gq;
                red[row * 4 + warp_n] = rmin[mt][h];
            }
    }
    __syncthreads();
    if (tid < 128) {
        float m = fminf(fminf(red[tid * 4 + 0], red[tid * 4 + 1]),
                        fminf(red[tid * 4 + 2], red[tid * 4 + 3]));
        out[(size_t)b * 16384 + y * 128 + tid] = m * 2.0f;
    }
}

extern "C" void kernel_launch(void* const* d_in, const int* in_sizes, int n_in,
                              void* d_out, int out_size)
{
    const float* x  = (const float*)d_in[0];
    const float* Wt = (const float*)d_in[1];
    float* out = (float*)d_out;

    cudaFuncSetAttribute(conv_min_mma13_kernel,
                         cudaFuncAttributeMaxDynamicSharedMemorySize, SMEM_TOTAL);

    xq_kernel<<<16640, TPB>>>(x);                  // 32*16*128*65 / 256
    wxform_kernel<<<(4 * 18432 + TPB - 1) / TPB, TPB>>>(Wt);

    dim3 grid(128, 32);   // rows x batch
    conv_min_mma13_kernel<<<grid, TPB, SMEM_TOTAL>>>(out);
}